// round 17
// baseline (speedup 1.0000x reference)
#include <cuda_runtime.h>
#include <math.h>

#define NH 25
#define NS 20
#define DT (1.0f/60.0f)
#define EPS_ 1e-4f
#define PQ 5.0f
#define QV_ 200.0f
#define QA_ 1.0f

#define WARPS 8
#define TROWS (WARPS * 32)        // 256 rows per tile
#define NTILE 4                   // tiles per block, 4-deep cp.async pipeline
#define RPB (NTILE * TROWS)       // 1024 rows per block
#define NCOEF 68                  // q[25] | beta[20] | gamma[20] | pad[3]
#define SMEM_BYTES (NTILE * TROWS * NH * 4)   // 102400 B dynamic

__device__ float d_coef[NCOEF];
__device__ unsigned d_flags[32 * 32];   // replicated flag, one per 128B line

__device__ __forceinline__ unsigned smem_u32(const void* p) {
    return (unsigned)__cvta_generic_to_shared(p);
}
__device__ __forceinline__ unsigned ld_acquire(const unsigned* p) {
    unsigned v;
    asm volatile("ld.global.acquire.gpu.b32 %0, [%1];" : "=r"(v) : "l"(p));
    return v;
}
__device__ __forceinline__ void st_release(unsigned* p, unsigned v) {
    asm volatile("st.global.release.gpu.b32 [%0], %1;" :: "l"(p), "r"(v));
}
template <int N>
__device__ __forceinline__ void wait_group() {
    asm volatile("cp.async.wait_group %0;\n" :: "n"(N));
}

// ---------------------------------------------------------------------------
// Coefficient solve: one warp, registers + shuffles (verified rel_err 6.6e-7
// since R4). Runs once on block 0 overlapped with the grid's staging.
// ---------------------------------------------------------------------------
__device__ __noinline__ void solve_coeffs(const float* __restrict__ Af,
                                          const float* __restrict__ Lq, int lane) {
    const unsigned FULL = 0xffffffffu;
    const int lnh = (lane < NH) ? lane : 0;
    const float af = (lane < NH) ? Af[lane] : 0.0f;

    float tk = 0.0f;
    #pragma unroll
    for (int j = 0; j < NH; j++)
        tk = fmaf(Lq[j * NH + lnh], __shfl_sync(FULL, af, j), tk);

    float q = EPS_ * af;
    #pragma unroll
    for (int k = 0; k < NH; k++)
        q = fmaf(Lq[lnh * NH + k], __shfl_sync(FULL, tk, k), q);
    if (lane < NH) d_coef[lane] = q;

    float av = (lane < NH) ? q * af : 0.0f;
    #pragma unroll
    for (int o = 16; o; o >>= 1) av += __shfl_xor_sync(FULL, av, o);
    const float alpha = av;

    float M0 = 0.f, M1 = 0.f, M2 = 0.f;
    for (int r = lane; r < NS; r++) {
        float w = (r == NS - 1) ? PQ : 1.0f;
        float d = (float)(r - lane);
        M0 += w;
        M1 = fmaf(w, d, M1);
        M2 = fmaf(w, d * d, M2);
    }

    float R[NS];
    #pragma unroll
    for (int c2 = 0; c2 < NS; c2++) {
        int m = lane > c2 ? lane : c2;
        if (m >= NS) m = NS - 1;
        float m0 = __shfl_sync(FULL, M0, m);
        float m1 = __shfl_sync(FULL, M1, m);
        float m2 = __shfl_sync(FULL, M2, m);
        float dd = fabsf((float)(lane - c2));
        float v = 2.0f * DT * DT * fmaf(alpha, fmaf(dd, m1, m2), QV_ * m0);
        if (lane == c2) v += 2.0f * QA_ + EPS_;
        R[c2] = v;
    }
    float b1 = M1;
    float b2 = fmaf(alpha, fmaf((float)(lane + 1), M1, M2), QV_ * M0);

    float myinv = 1.0f;
    #pragma unroll
    for (int k = 0; k < NS; k++) {
        float pk = __shfl_sync(FULL, R[k], k);
        float inv = __frcp_rn(pk);
        float f = R[k] * inv;
        if (lane == k) { myinv = inv; f = 0.0f; }
        #pragma unroll
        for (int j = k + 1; j < NS; j++) {
            float pj = __shfl_sync(FULL, R[j], k);
            R[j] = fmaf(-f, pj, R[j]);
        }
        float p1 = __shfl_sync(FULL, b1, k);
        float p2 = __shfl_sync(FULL, b2, k);
        b1 = fmaf(-f, p1, b1);
        b2 = fmaf(-f, p2, b2);
    }
    float h1 = b1 * myinv;
    float h2 = b2 * myinv;

    float ab = 0.f, ag = 0.f;
    #pragma unroll
    for (int c = 0; c < NS; c++) {
        float hc = __shfl_sync(FULL, h1, c);
        float gc = __shfl_sync(FULL, h2, c);
        if (c <= lane) {
            float w = (float)(lane - c) + 0.5f;
            ab = fmaf(w, hc, ab);
            ag = fmaf(w, gc, ag);
        }
    }
    if (lane < NS) {
        const float f = 2.0f * DT * DT * DT;
        d_coef[NH + lane]      = -f * ab;                              // beta  [25,45)
        d_coef[NH + NS + lane] = fmaf((float)(lane + 1), DT, -f * ag); // gamma [45,65)
    }
    if (lane >= 29) d_coef[65 + (lane - 29)] = 0.0f;   // pad [65,68) only
}

// ---------------------------------------------------------------------------
// Fused kernel, 4-deep pipeline: each row-block handles 4 tiles of 256 rows.
// All four tiles' cp.async groups issued up front (12.8 KB in flight per
// warp); earlier tiles' compute+store overlaps later tiles' DRAM reads.
// Per-warp regions; warps fully independent.
// ---------------------------------------------------------------------------
__global__ void __launch_bounds__(TROWS) mpc_fused(
    const float* __restrict__ x, const float* __restrict__ gp,
    const float* __restrict__ gv, const float* __restrict__ Af,
    const float* __restrict__ Lq, float* __restrict__ out, int nB)
{
    extern __shared__ float sx[];        // NTILE * 256 * 25 floats = 102.4 KB
    __shared__ float scoef[NCOEF];

    const int t = threadIdx.x;
    const int warp = t >> 5;
    const int lane = t & 31;

    if (blockIdx.x == 0) {
        if (warp == 0) {
            solve_coeffs(Af, Lq, lane);
            __threadfence();
            __syncwarp();
            st_release(&d_flags[lane * 32], 1u);   // 32 replicas
        }
        return;
    }

    const int bid = blockIdx.x - 1;
    const long long n4_total = (long long)nB * NH / 4;

    int wbase[NTILE];
    // 1) issue ALL tiles' staging (one commit group per tile)
    #pragma unroll
    for (int tt = 0; tt < NTILE; tt++) {
        wbase[tt] = (bid * NTILE + tt) * TROWS + warp * 32;
        const float4* __restrict__ xin = (const float4*)(x + (size_t)wbase[tt] * NH);
        float* wreg = sx + tt * TROWS * NH + warp * 32 * NH;
        const long long i4base = (long long)wbase[tt] * NH / 4;
        #pragma unroll
        for (int i = lane; i < 32 * NH / 4; i += 32) {
            if (i4base + i < n4_total) {
                unsigned d = smem_u32(wreg + 4 * i);
                asm volatile("cp.async.cg.shared.global [%0], [%1], 16;\n"
                             :: "r"(d), "l"(xin + i));
            }
        }
        asm volatile("cp.async.commit_group;\n");
    }

    // 2) prefetch gp/gv for all tiles
    float pv[NTILE], vv[NTILE];
    #pragma unroll
    for (int tt = 0; tt < NTILE; tt++) {
        const int b = wbase[tt] + lane;
        const bool live = (b < nB);
        pv[tt] = live ? gp[b] : 0.f;
        vv[tt] = live ? gv[b] : 0.f;
    }

    // 3) coefficient readiness (hashed flag line; warp-uniform -> 1 request)
    {
        const unsigned* fp = &d_flags[(blockIdx.x & 31) * 32];
        if (ld_acquire(fp) == 0u) {
            while (ld_acquire(fp) == 0u) { __nanosleep(128); }
        }
    }

    // 4) coefficients -> smem (per-warp redundant copy; identical values)
    #pragma unroll
    for (int i = lane; i < NCOEF; i += 32) scoef[i] = d_coef[i];
    __syncwarp();

    const float* __restrict__ sq = scoef;
    const float* __restrict__ sb = scoef + NH;
    const float* __restrict__ sg = scoef + NH + NS;

    // 5) drain pipeline: compute+store tile tt while tiles >tt still load
    #pragma unroll
    for (int tt = 0; tt < NTILE; tt++) {
        switch (tt) {     // compile-time: pending groups after this wait
            case 0: wait_group<NTILE - 1>(); break;
            case 1: wait_group<NTILE - 2>(); break;
            case 2: wait_group<NTILE - 3>(); break;
            default: wait_group<0>(); break;
        }
        __syncwarp();

        float* __restrict__ wreg = sx + tt * TROWS * NH + warp * 32 * NH;
        const float* __restrict__ xr = wreg + lane * NH;   // stride 25: conflict-free

        float y0 = 0.f, y1 = 0.f;
        #pragma unroll
        for (int j = 0; j < 24; j += 2) {
            y0 = fmaf(xr[j],     sq[j],     y0);
            y1 = fmaf(xr[j + 1], sq[j + 1], y1);
        }
        const float y = fmaf(xr[24], sq[24], y0) + y1;
        const float p = pv[tt];
        const float v = vv[tt];

        __syncwarp();   // own-region reads complete before overwrite

        // outputs packed at lane*20 in own region (80B rows, 16B aligned)
        float4* so4 = (float4*)(wreg + lane * NS);
        #pragma unroll
        for (int s4 = 0; s4 < NS / 4; s4++) {
            float4 r;
            r.x = fmaf(sb[4*s4 + 0], y, fmaf(sg[4*s4 + 0], v, p));
            r.y = fmaf(sb[4*s4 + 1], y, fmaf(sg[4*s4 + 1], v, p));
            r.z = fmaf(sb[4*s4 + 2], y, fmaf(sg[4*s4 + 2], v, p));
            r.w = fmaf(sb[4*s4 + 3], y, fmaf(sg[4*s4 + 3], v, p));
            so4[s4] = r;
        }
        __syncwarp();

        // coalesced copy out: 32 rows * 20 floats = 160 contiguous float4
        float4* __restrict__ o4 = (float4*)(out + (size_t)wbase[tt] * NS);
        const float4* so = (const float4*)wreg;
        const long long o4_total = (long long)nB * NS / 4;
        const long long o4base = (long long)wbase[tt] * NS / 4;
        #pragma unroll
        for (int i = lane; i < 32 * NS / 4; i += 32) {
            if (o4base + i < o4_total) o4[i] = so[i];
        }
        __syncwarp();
    }
}

extern "C" void kernel_launch(void* const* d_in, const int* in_sizes, int n_in,
                              void* d_out, int out_size) {
    const float* x  = (const float*)d_in[0];
    const float* gp = (const float*)d_in[1];
    const float* gv = (const float*)d_in[2];
    const float* Af = (const float*)d_in[3];
    const float* Lq = (const float*)d_in[4];
    float* out = (float*)d_out;

    const int nB = in_sizes[0] / NH;

    cudaFuncSetAttribute(mpc_fused, cudaFuncAttributeMaxDynamicSharedMemorySize,
                         SMEM_BYTES);
    const int grid = (nB + RPB - 1) / RPB + 1;   // +1: solver block
    mpc_fused<<<grid, TROWS, SMEM_BYTES>>>(x, gp, gv, Af, Lq, out, nB);
}